// round 15
// baseline (speedup 1.0000x reference)
#include <cuda_runtime.h>
#include <cstdint>

// Blur_82471962018173: depthwise 4x4 FIR on (4,128,513,513) fp32 -> (4,128,512,512)
// Separable: w_j = k[0][j], u_i = k[i][0]/k[0][0] (exact: rank-1 dyadic kernel).
//
// R15: slab-interleaved staging. R9/R11 plateau at ~5.5TB/s because each CTA
// issues ALL reads up-front then only writes during compute; wave-aligned CTAs
// make the SM's DRAM stream oscillate read-burst/write-burst (~70% duty).
// Here the 19-row flat stage is committed as 8 cp.async groups (5,2,2,...,2
// rows); the compute loop commits slab s+3, waits group<=3, computes 2 output
// rows -> reads issue steadily across the CTA lifetime and mix with writes.
// No ring modulo, no 4B copies (R10's failure modes); same flat absolute-offset
// 16B cp.async addressing as R9. 39KB smem / 512 thr / 4 CTAs/SM / <=32 regs.

#define W_IN  513
#define H_IN  513
#define W_OUT 512
#define H_OUT 512
#define TILE_ROWS 16
#define IN_ROWS   (TILE_ROWS + 3)          // 19 staged input rows
#define STAGE_FLOATS (IN_ROWS * W_IN)      // 9747
#define SMEM_FLOATS  (STAGE_FLOATS + 8)
#define NT 512
#define SLABS 8                            // slab 0: lr [0,5); slab s: [2s+3, 2s+5)

__global__ __launch_bounds__(NT, 4)
void blur_slab_kernel(const float* __restrict__ in,
                      const float* __restrict__ kern,
                      float* __restrict__ out)
{
    __shared__ __align__(16) float sm[SMEM_FLOATS];

    const int img = blockIdx.y;
    const int y0  = blockIdx.x * TILE_ROWS;
    const long gbase = (long)img * (W_IN * H_IN);
    float* __restrict__ op = out + (size_t)img * (W_OUT * H_OUT);
    const int tid = threadIdx.x;

    // Separable factorization (uniform across threads)
    const float w0 = __ldg(kern + 0);
    const float w1 = __ldg(kern + 1);
    const float w2 = __ldg(kern + 2);
    const float w3 = __ldg(kern + 3);
    const float inv = 1.0f / w0;
    const float u1 = __ldg(kern + 4)  * inv;
    const float u2 = __ldg(kern + 8)  * inv;
    const float u3 = __ldg(kern + 12) * inv;   // u0 == 1

    // Flat staged region, ABSOLUTE offsets from tensor base (alloc-aligned):
    // smem[i] holds absolute flat position aorg + i - shift.
    const int  r_lo = y0 - 1;
    const long aorg = gbase + (long)r_lo * W_IN;          // may be -513 (img 0)
    const int  shift = (int)(((aorg % 4) + 4) & 3);
    const int  v_lo = (r_lo < 0) ? 0 : r_lo;
    const int  v_hi = (y0 + IN_ROWS - 1 < H_IN) ? (y0 + IN_ROWS - 1) : H_IN;
    const long aflat_lo = gbase + (long)v_lo * W_IN;
    const long aflat_hi = gbase + (long)v_hi * W_IN;
    const int  s_lo = (int)(aflat_lo - aorg) + shift;
    const int  s_hi = (int)(aflat_hi - aorg) + shift;

    // Zero-fill smem head/tail (nonempty only for first/last row-tiles);
    // disjoint from all cp.async destinations, visible at the first bar.
    for (int i = tid; i < s_lo; i += NT) sm[i] = 0.f;
    for (int i = s_hi + tid; i < STAGE_FLOATS + shift; i += NT) sm[i] = 0.f;

    // Stage clamped absolute range [lo,hi): scalar head/tail (<=3 floats),
    // 16B cp.async interior. Caller commits the group (possibly empty).
    auto stage_range = [&](long lo, long hi) {
        if (lo >= hi) return;
        const long a0 = (lo + 3) & ~3L;
        const long a1 = hi & ~3L;
        for (long f = lo + tid; f < a0; f += NT)
            sm[(int)(f - aorg) + shift] = __ldg(in + f);
        for (long f = a1 + tid; f < hi; f += NT)
            sm[(int)(f - aorg) + shift] = __ldg(in + f);
        const unsigned int n4 = (unsigned int)((a1 - a0) >> 2);
        const float4* __restrict__ gsrc = reinterpret_cast<const float4*>(in + a0);
        const unsigned int sbase =
            (unsigned int)__cvta_generic_to_shared(sm + ((int)(a0 - aorg) + shift));
        for (unsigned int i = (unsigned int)tid; i < n4; i += NT) {
            asm volatile("cp.async.cg.shared.global [%0], [%1], 16;\n"
                         :: "r"(sbase + i * 16u), "l"(gsrc + i));
        }
    };

    auto stage_slab = [&](int s) {
        const int l0 = (s == 0) ? 0 : (2 * s + 3);
        const int l1 = 2 * s + 5;
        long lo = aorg + (long)l0 * W_IN; if (lo < aflat_lo) lo = aflat_lo;
        long hi = aorg + (long)l1 * W_IN; if (hi > aflat_hi) hi = aflat_hi;
        stage_range(lo, hi);
        asm volatile("cp.async.commit_group;\n" ::: "memory");
    };

    // Prologue: slabs 0..2 in flight (prefetch distance 3).
    stage_slab(0);
    stage_slab(1);
    stage_slab(2);

    // Compute: one output column per thread, 2 rows per slab.
    const int x   = tid;
    const bool lok = (x > 0);
    const bool rok = (x < W_OUT - 1);
    const float* __restrict__ sb = sm + shift + x;

    auto hrow = [&](int lr) -> float {
        const float* __restrict__ row = sb + lr * W_IN;
        const float a0 = lok ? row[-1] : 0.f;
        const float a1 = row[0];
        const float a2 = row[1];
        const float a3 = rok ? row[2] : 0.f;
        return fmaf(w0, a0, fmaf(w1, a1, fmaf(w2, a2, w3 * a3)));
    };

    float h0, h1, h2;
    float* __restrict__ orow = op + (size_t)y0 * W_OUT + x;

    #pragma unroll
    for (int s = 0; s < SLABS; ++s) {
        // Keep the read stream flowing: commit slab s+3, then ensure slab s done.
        if (s + 3 < SLABS) {
            stage_slab(s + 3);
            asm volatile("cp.async.wait_group 3;\n" ::: "memory");
        } else if (SLABS - 1 - s == 2) {
            asm volatile("cp.async.wait_group 2;\n" ::: "memory");
        } else if (SLABS - 1 - s == 1) {
            asm volatile("cp.async.wait_group 1;\n" ::: "memory");
        } else {
            asm volatile("cp.async.wait_group 0;\n" ::: "memory");
        }
        __syncthreads();   // slab s (and zero STS) visible to all threads

        if (s == 0) { h0 = hrow(0); h1 = hrow(1); h2 = hrow(2); }

        // Output rows 2s and 2s+1 (need staged lr up to 2s+4, inside slab s).
        #pragma unroll
        for (int r = 2 * s; r < 2 * s + 2; ++r) {
            const float h3 = hrow(r + 3);
            float o = fmaf(u1, h1, h0);
            o = fmaf(u2, h2, o);
            o = fmaf(u3, h3, o);
            orow[(size_t)r * W_OUT] = o;
            h0 = h1; h1 = h2; h2 = h3;
        }
        // No second bar: staged slots are never overwritten (flat buffer).
    }
}

extern "C" void kernel_launch(void* const* d_in, const int* in_sizes, int n_in,
                              void* d_out, int out_size)
{
    (void)n_in; (void)out_size;
    const float* input  = (const float*)d_in[0];
    const float* kernel = (const float*)d_in[1];
    float*       output = (float*)d_out;

    const int n_images = in_sizes[0] / (W_IN * H_IN);   // N*C = 512

    dim3 block(NT, 1, 1);
    dim3 grid(H_OUT / TILE_ROWS, n_images, 1);          // (32, 512)
    blur_slab_kernel<<<grid, block>>>(input, kernel, output);
}

// round 16
// speedup vs baseline: 1.8957x; 1.8957x over previous
#include <cuda_runtime.h>
#include <cstdint>

// Blur_82471962018173: depthwise 4x4 FIR on (4,128,513,513) fp32 -> (4,128,512,512)
// Separable: w_j = k[0][j], u_i = k[i][0]/k[0][0] (exact: rank-1 dyadic kernel).
//
// R16 = R9 structure (the measured optimum: all reads in flight at once, 4
// CTAs/SM) with: TILE_ROWS 16->24 (fewer CTA prologues, -5% halo traffic, more
// bytes in flight per CTA; dynamic smem 55.4KB, still 4 CTAs/SM = 2048 thr,
// 32 regs = full regfile) and __stcs streaming output stores (output is never
// re-read; keep L2 for the halo-sharing read stream). 512 = 21*24+8 so the
// last y-tile computes 8 rows (runtime row count, outer loop step 8).

#define W_IN  513
#define H_IN  513
#define W_OUT 512
#define H_OUT 512
#define TILE_ROWS 24
#define IN_ROWS   (TILE_ROWS + 3)          // 27 staged input rows
#define STAGE_FLOATS (IN_ROWS * W_IN)      // 13851
#define SMEM_FLOATS  (STAGE_FLOATS + 8)    // + shift(<=3) + pad
#define NT 512
#define NTILES_Y ((H_OUT + TILE_ROWS - 1) / TILE_ROWS)   // 22

__global__ __launch_bounds__(NT, 4)
void blur_t24_kernel(const float* __restrict__ in,
                     const float* __restrict__ kern,
                     float* __restrict__ out)
{
    extern __shared__ __align__(16) float sm[];   // SMEM_FLOATS floats

    const int img = blockIdx.y;
    const int y0  = blockIdx.x * TILE_ROWS;
    const int nr  = (H_OUT - y0 < TILE_ROWS) ? (H_OUT - y0) : TILE_ROWS;  // 24 or 8
    const long gbase = (long)img * (W_IN * H_IN);
    float* __restrict__ op = out + (size_t)img * (W_OUT * H_OUT);
    const int tid = threadIdx.x;

    // Separable factorization (uniform across threads)
    const float w0 = __ldg(kern + 0);
    const float w1 = __ldg(kern + 1);
    const float w2 = __ldg(kern + 2);
    const float w3 = __ldg(kern + 3);
    const float inv = 1.0f / w0;
    const float u1 = __ldg(kern + 4)  * inv;
    const float u2 = __ldg(kern + 8)  * inv;
    const float u3 = __ldg(kern + 12) * inv;   // u0 == 1

    // ---- Flat staged region, ABSOLUTE offsets from tensor base `in`
    // (allocation-aligned; absolute flat idx ≡ 0 mod 4 => 16B aligned).
    // smem[i] holds absolute flat position aorg + i - shift.
    const int  r_lo = y0 - 1;
    const long aorg = gbase + (long)r_lo * W_IN;          // may be -513 (img 0)
    const int  shift = (int)(((aorg % 4) + 4) & 3);
    const int  v_lo = (r_lo < 0) ? 0 : r_lo;
    const int  v_hi = (y0 + IN_ROWS - 1 < H_IN) ? (y0 + IN_ROWS - 1) : H_IN;
    const long aflat_lo = gbase + (long)v_lo * W_IN;      // first valid abs idx
    const long aflat_hi = gbase + (long)v_hi * W_IN;      // one past last valid
    const int  s_lo = (int)(aflat_lo - aorg) + shift;
    const int  s_hi = (int)(aflat_hi - aorg) + shift;

    // Zero-fill smem head/tail (nonempty only for first/last row-tiles)
    for (int i = tid; i < s_lo; i += NT) sm[i] = 0.f;
    for (int i = s_hi + tid; i < STAGE_FLOATS + shift; i += NT) sm[i] = 0.f;

    // Stage everything at once (max MLP — the measured optimum):
    // scalar head/tail (<=3 floats each), 16B cp.async interior.
    {
        const long a0 = (aflat_lo + 3) & ~3L;
        const long a1 = aflat_hi & ~3L;
        for (long f = aflat_lo + tid; f < a0; f += NT)
            sm[(int)(f - aorg) + shift] = __ldg(in + f);
        for (long f = a1 + tid; f < aflat_hi; f += NT)
            sm[(int)(f - aorg) + shift] = __ldg(in + f);

        const unsigned int n4 = (unsigned int)((a1 - a0) >> 2);
        const float4* __restrict__ gsrc = reinterpret_cast<const float4*>(in + a0);
        const unsigned int sbase =
            (unsigned int)__cvta_generic_to_shared(sm + ((int)(a0 - aorg) + shift));
        for (unsigned int i = (unsigned int)tid; i < n4; i += NT) {
            asm volatile("cp.async.cg.shared.global [%0], [%1], 16;\n"
                         :: "r"(sbase + i * 16u), "l"(gsrc + i));
        }
        asm volatile("cp.async.commit_group;\n" ::: "memory");
        asm volatile("cp.async.wait_group 0;\n" ::: "memory");
    }
    __syncthreads();

    // ---- Compute: one output column per thread, nr rows streamed.
    const int x   = tid;
    const bool lok = (x > 0);
    const bool rok = (x < W_OUT - 1);
    const float* __restrict__ sb = sm + shift + x;

    auto hrow = [&](int lr) -> float {
        const float* __restrict__ row = sb + lr * W_IN;
        const float a0 = lok ? row[-1] : 0.f;
        const float a1 = row[0];
        const float a2 = row[1];
        const float a3 = rok ? row[2] : 0.f;
        return fmaf(w0, a0, fmaf(w1, a1, fmaf(w2, a2, w3 * a3)));
    };

    float h0 = hrow(0);
    float h1 = hrow(1);
    float h2 = hrow(2);

    float* __restrict__ orow = op + (size_t)y0 * W_OUT + x;
    for (int rb = 0; rb < nr; rb += 8) {       // nr in {8, 24}
        #pragma unroll
        for (int rr = 0; rr < 8; ++rr) {
            const int r = rb + rr;
            const float h3 = hrow(r + 3);
            float o = fmaf(u1, h1, h0);
            o = fmaf(u2, h2, o);
            o = fmaf(u3, h3, o);
            __stcs(orow + (size_t)r * W_OUT, o);   // streaming: never re-read
            h0 = h1; h1 = h2; h2 = h3;
        }
    }
}

extern "C" void kernel_launch(void* const* d_in, const int* in_sizes, int n_in,
                              void* d_out, int out_size)
{
    (void)n_in; (void)out_size;
    const float* input  = (const float*)d_in[0];
    const float* kernel = (const float*)d_in[1];
    float*       output = (float*)d_out;

    const int n_images = in_sizes[0] / (W_IN * H_IN);   // N*C = 512

    const int smem_bytes = SMEM_FLOATS * (int)sizeof(float);   // 55436
    cudaFuncSetAttribute(blur_t24_kernel,
                         cudaFuncAttributeMaxDynamicSharedMemorySize, smem_bytes);

    dim3 block(NT, 1, 1);
    dim3 grid(NTILES_Y, n_images, 1);                   // (22, 512)
    blur_t24_kernel<<<grid, block, smem_bytes>>>(input, kernel, output);
}